// round 1
// baseline (speedup 1.0000x reference)
#include <cuda_runtime.h>
#include <cuda_bf16.h>
#include <math.h>

// Problem constants (fixed by the reference setup)
#define NB   128          // dialogs
#define LL   256          // dialog length
#define NN   (NB*LL)      // 32768 nodes
#define DIN  1024
#define HH   256
#define CC   7
#define WIN  4            // past/future window

// ---------------- scratch (device globals; no allocation allowed) ----------
__device__ __align__(256) float g_t_all[(size_t)NN * 1024];   // [t0|t1|root|skip] per node
__device__ __align__(256) float g_hc[(size_t)NN * 512];       // [neigh | h] per node
__device__ __align__(256) float g_z[(size_t)NN * HH];         // GraphConv GEMM out
__device__ __align__(256) float g_Bcat1[1024 * 1024];         // [Wr0|Wr1|Wroot|Wskip]
__device__ __align__(256) float g_Bcat2[512 * 256];           // [Wrel; Wgrt]
__device__ float g_loss;

// ---------------- prep: build concatenated weights, zero loss --------------
__global__ void prep_kernel(const float* __restrict__ Wrgcn,
                            const float* __restrict__ Wroot,
                            const float* __restrict__ Wskip,
                            const float* __restrict__ Wrel,
                            const float* __restrict__ Wgrt) {
    int idx = blockIdx.x * blockDim.x + threadIdx.x;
    if (idx == 0) g_loss = 0.0f;
    if (idx < 1024 * 1024) {
        int k = idx >> 10, col = idx & 1023;
        int g = col >> 8, c = col & 255;
        float v;
        if      (g == 0) v = Wrgcn[k * 256 + c];
        else if (g == 1) v = Wrgcn[262144 + k * 256 + c];
        else if (g == 2) v = Wroot[k * 256 + c];
        else             v = Wskip[k * 256 + c];
        g_Bcat1[idx] = v;
    }
    if (idx < 512 * 256) {
        int k = idx >> 8, c = idx & 255;
        g_Bcat2[idx] = (k < 256) ? Wrel[k * 256 + c] : Wgrt[(k - 256) * 256 + c];
    }
}

// ---------------- 128x128x8 fp32 SGEMM, 8x8 per thread ---------------------
__global__ __launch_bounds__(256, 2)
void sgemm128(const float* __restrict__ A, const float* __restrict__ B,
              float* __restrict__ C, int M, int N, int K) {
    __shared__ __align__(16) float As[8][132];   // padded: conflict-free transpose store
    __shared__ __align__(16) float Bs[8][128];

    const int tid = threadIdx.x;
    const int tx = tid & 15, ty = tid >> 4;
    const int rowBase = blockIdx.x * 128;
    const int colBase = blockIdx.y * 128;

    float acc[8][8];
#pragma unroll
    for (int i = 0; i < 8; i++)
#pragma unroll
        for (int j = 0; j < 8; j++) acc[i][j] = 0.0f;

    const int ar = tid >> 1;          // A loader: row within tile
    const int ac = (tid & 1) * 4;     // A loader: k offset (float4)
    const int br = tid >> 5;          // B loader: k row
    const int bc = (tid & 31) * 4;    // B loader: col offset (float4)

    const float* Ag = A + (size_t)(rowBase + ar) * K + ac;
    const float* Bg = B + (size_t)br * N + colBase + bc;

    for (int k0 = 0; k0 < K; k0 += 8) {
        float4 av = *(const float4*)(Ag + k0);
        float4 bv = *(const float4*)(Bg + (size_t)k0 * N);
        As[ac + 0][ar] = av.x;
        As[ac + 1][ar] = av.y;
        As[ac + 2][ar] = av.z;
        As[ac + 3][ar] = av.w;
        *(float4*)&Bs[br][bc] = bv;
        __syncthreads();
#pragma unroll
        for (int k = 0; k < 8; k++) {
            float a[8], b[8];
            *(float4*)&a[0] = *(const float4*)&As[k][ty * 8];
            *(float4*)&a[4] = *(const float4*)&As[k][ty * 8 + 4];
            *(float4*)&b[0] = *(const float4*)&Bs[k][tx * 8];
            *(float4*)&b[4] = *(const float4*)&Bs[k][tx * 8 + 4];
#pragma unroll
            for (int i = 0; i < 8; i++)
#pragma unroll
                for (int j = 0; j < 8; j++) acc[i][j] = fmaf(a[i], b[j], acc[i][j]);
        }
        __syncthreads();
    }
#pragma unroll
    for (int i = 0; i < 8; i++) {
        float* Crow = C + (size_t)(rowBase + ty * 8 + i) * N + colBase + tx * 8;
        *(float4*)(Crow)     = make_float4(acc[i][0], acc[i][1], acc[i][2], acc[i][3]);
        *(float4*)(Crow + 4) = make_float4(acc[i][4], acc[i][5], acc[i][6], acc[i][7]);
    }
}

// ---------------- RGCN window aggregation (mean per relation) --------------
// h[i] = root[i] + b_rgcn + sum0/max(c0,1) + sum1/max(c1,1); stored in hc[i][256..512)
__global__ void rgcn_agg(const int* __restrict__ spk, const float* __restrict__ b_rgcn) {
    int i = blockIdx.x;
    int c = threadIdx.x;
    int p = i & (LL - 1);
    int dlo = (p < WIN) ? -p : -WIN;
    int dhi = ((LL - 1 - p) < WIN) ? (LL - 1 - p) : WIN;
    int si = spk[i];
    float s0 = 0.f, s1 = 0.f;
    int c0 = 0, c1 = 0;
    for (int d = dlo; d <= dhi; d++) {
        int j = i + d;
        int r = si & spk[j];                    // speakers are {0,1}: product == AND
        float v = g_t_all[(size_t)j * 1024 + r * 256 + c];
        if (r) { s1 += v; c1++; } else { s0 += v; c0++; }
    }
    float h = g_t_all[(size_t)i * 1024 + 512 + c] + b_rgcn[c]
            + s0 / (float)(c0 > 0 ? c0 : 1)
            + s1 / (float)(c1 > 0 ? c1 : 1);
    g_hc[(size_t)i * 512 + 256 + c] = h;
}

// ---------------- GraphConv neighbor add-aggregation -----------------------
// neigh[i] = sum_{j in window(i)} h[j]; stored in hc[i][0..256)
__global__ void graph_sum() {
    int i = blockIdx.x;
    int c = threadIdx.x;
    int p = i & (LL - 1);
    int dlo = (p < WIN) ? -p : -WIN;
    int dhi = ((LL - 1 - p) < WIN) ? (LL - 1 - p) : WIN;
    float s = 0.f;
    for (int d = dlo; d <= dhi; d++)
        s += g_hc[(size_t)(i + d) * 512 + 256 + c];
    g_hc[(size_t)i * 512 + c] = s;
}

// ---------------- classifier + cross-entropy loss --------------------------
// pre[n] = z[n] + skip[n] + b_rel + b_skip; logits = pre@W_cls + b_cls
__global__ void classify_loss(const float* __restrict__ b_rel,
                              const float* __restrict__ b_skip,
                              const float* __restrict__ W_cls,
                              const float* __restrict__ b_cls,
                              const int* __restrict__ labels,
                              float* __restrict__ out_logits) {
    int n = blockIdx.x * 8 + (threadIdx.x >> 5);
    int lane = threadIdx.x & 31;
    const float* zrow = g_z + (size_t)n * HH;
    const float* srow = g_t_all + (size_t)n * 1024 + 768;

    float acc[CC] = {0.f, 0.f, 0.f, 0.f, 0.f, 0.f, 0.f};
    for (int e = lane; e < HH; e += 32) {
        float pre = zrow[e] + srow[e] + b_rel[e] + b_skip[e];
#pragma unroll
        for (int c = 0; c < CC; c++) acc[c] = fmaf(pre, W_cls[e * CC + c], acc[c]);
    }
#pragma unroll
    for (int off = 16; off; off >>= 1)
#pragma unroll
        for (int c = 0; c < CC; c++) acc[c] += __shfl_xor_sync(0xffffffffu, acc[c], off);
#pragma unroll
    for (int c = 0; c < CC; c++) acc[c] += b_cls[c];

    if (out_logits != nullptr && lane < CC)
        out_logits[(size_t)n * CC + lane] = acc[lane];

    __shared__ float wloss[8];
    if (lane == 0) {
        float m = acc[0];
#pragma unroll
        for (int c = 1; c < CC; c++) m = fmaxf(m, acc[c]);
        float s = 0.f;
#pragma unroll
        for (int c = 0; c < CC; c++) s += expf(acc[c] - m);
        float lse = m + logf(s);
        wloss[threadIdx.x >> 5] = lse - acc[labels[n]];
    }
    __syncthreads();
    if (threadIdx.x == 0) {
        float t = 0.f;
#pragma unroll
        for (int w = 0; w < 8; w++) t += wloss[w];
        atomicAdd(&g_loss, t);
    }
}

__global__ void finalize_loss(float* __restrict__ dst) {
    *dst = g_loss * (1.0f / (float)NN);
}

// ---------------- host launcher --------------------------------------------
static float* sym_addr(const void* sym) {
    void* p = nullptr;
    cudaGetSymbolAddress(&p, sym);
    return (float*)p;
}

extern "C" void kernel_launch(void* const* d_in, const int* in_sizes, int n_in,
                              void* d_out, int out_size) {
    const float* input   = (const float*)d_in[0];
    // d_in[1] dialog_lengths (all == LL, implied by structure)
    const int*   speakers= (const int*)d_in[2];
    const int*   labels  = (const int*)d_in[3];
    // d_in[4] edge_index, d_in[5] rel_type: deterministic window structure, recomputed
    const float* W_rgcn  = (const float*)d_in[6];
    const float* W_root  = (const float*)d_in[7];
    const float* b_rgcn  = (const float*)d_in[8];
    const float* W_rel   = (const float*)d_in[9];
    const float* b_rel   = (const float*)d_in[10];
    const float* W_grt   = (const float*)d_in[11];
    const float* W_skip  = (const float*)d_in[12];
    const float* b_skip  = (const float*)d_in[13];
    const float* W_cls   = (const float*)d_in[14];
    const float* b_cls   = (const float*)d_in[15];
    float* out = (float*)d_out;

    float* t_all = sym_addr(g_t_all);
    float* hc    = sym_addr(g_hc);
    float* z     = sym_addr(g_z);
    float* Bcat1 = sym_addr(g_Bcat1);
    float* Bcat2 = sym_addr(g_Bcat2);

    // 1) weight concat + loss zero
    prep_kernel<<<4096, 256>>>(W_rgcn, W_root, W_skip, W_rel, W_grt);

    // 2) fused input GEMM: [32768,1024] @ [1024,1024] -> [t0|t1|root|skip]
    sgemm128<<<dim3(NN / 128, 1024 / 128), 256>>>(input, Bcat1, t_all, NN, 1024, DIN);

    // 3) RGCN window mean-aggregation -> h
    rgcn_agg<<<NN, HH>>>(speakers, b_rgcn);

    // 4) GraphConv window add-aggregation -> neigh
    graph_sum<<<NN, HH>>>();

    // 5) [neigh|h] @ [W_rel;W_grt]: [32768,512] @ [512,256]
    sgemm128<<<dim3(NN / 128, 256 / 128), 256>>>(hc, Bcat2, z, NN, HH, 512);

    // 6) classifier + loss
    float* logits = (out_size >= NN * CC) ? out : nullptr;
    classify_loss<<<NN / 8, 256>>>(b_rel, b_skip, W_cls, b_cls, labels, logits);

    // 7) loss scalar placement
    if (out_size == NN * CC + 1)       finalize_loss<<<1, 1>>>(out + (size_t)NN * CC);
    else if (out_size < NN * CC)       finalize_loss<<<1, 1>>>(out);
}

// round 4
// speedup vs baseline: 1.6912x; 1.6912x over previous
#include <cuda_runtime.h>
#include <cuda_bf16.h>
#include <cuda_pipeline.h>
#include <mma.h>
#include <math.h>

using namespace nvcuda;

// Problem constants (fixed by the reference setup)
#define NB   128          // dialogs
#define LL   256          // dialog length
#define NN   (NB*LL)      // 32768 nodes
#define DIN  1024
#define HH   256
#define CC   7
#define WIN  4            // past/future window

// GEMM tiling
#define BM 128
#define BN 128
#define BK 16
#define APITCH 24         // floats per A smem row (BK + 8 pad; ldm multiple of 8)
#define BPITCH 136        // floats per B smem row (BN + 8 pad; ldm multiple of 8)
#define NSTAGES 4
#define SA (BM*APITCH)    // 3072 floats per A stage
#define SB (BK*BPITCH)    // 2176 floats per B stage
#define SMEM_BYTES ((NSTAGES*(SA+SB))*4)   // 83968

// ---------------- scratch (device globals; no allocation allowed) ----------
__device__ __align__(256) float g_Ain[(size_t)NN * DIN];      // tf32-rounded input
__device__ __align__(256) float g_t_all[(size_t)NN * 1024];   // [t0|t1|root|skip]
__device__ __align__(256) float g_hc[(size_t)NN * 512];       // [neigh | h] (tf32-rounded)
__device__ __align__(256) float g_z[(size_t)NN * HH];         // GraphConv GEMM out
__device__ __align__(256) float g_Bcat1[1024 * 1024];         // [Wr0|Wr1|Wroot|Wskip] tf32
__device__ __align__(256) float g_Bcat2[512 * 256];           // [Wrel; Wgrt] tf32
__device__ float g_loss;

// ---------------- prep: concatenated tf32 weights, zero loss ---------------
__global__ void prep_kernel(const float* __restrict__ Wrgcn,
                            const float* __restrict__ Wroot,
                            const float* __restrict__ Wskip,
                            const float* __restrict__ Wrel,
                            const float* __restrict__ Wgrt) {
    int idx = blockIdx.x * blockDim.x + threadIdx.x;
    if (idx == 0) g_loss = 0.0f;
    if (idx < 1024 * 1024) {
        int k = idx >> 10, col = idx & 1023;
        int g = col >> 8, c = col & 255;
        float v;
        if      (g == 0) v = Wrgcn[k * 256 + c];
        else if (g == 1) v = Wrgcn[262144 + k * 256 + c];
        else if (g == 2) v = Wroot[k * 256 + c];
        else             v = Wskip[k * 256 + c];
        g_Bcat1[idx] = wmma::__float_to_tf32(v);
    }
    if (idx < 512 * 256) {
        int k = idx >> 8, c = idx & 255;
        float v = (k < 256) ? Wrel[k * 256 + c] : Wgrt[(k - 256) * 256 + c];
        g_Bcat2[idx] = wmma::__float_to_tf32(v);
    }
}

// ---------------- tf32-round the input matrix ------------------------------
__global__ void cvtA_kernel(const float4* __restrict__ in, float4* __restrict__ out) {
    int n4 = NN * DIN / 4;
    for (int i = blockIdx.x * blockDim.x + threadIdx.x; i < n4; i += gridDim.x * blockDim.x) {
        float4 v = in[i];
        v.x = wmma::__float_to_tf32(v.x);
        v.y = wmma::__float_to_tf32(v.y);
        v.z = wmma::__float_to_tf32(v.z);
        v.w = wmma::__float_to_tf32(v.w);
        out[i] = v;
    }
}

// ---------------- TF32 wmma GEMM, 128x128 tile, 4-stage async pipeline -----
// blockIdx.x = N tile (fast-varying -> concurrent column tiles reuse A via L2)
// blockIdx.y = M tile
__global__ __launch_bounds__(256, 2)
void tf32gemm(const float* __restrict__ A, const float* __restrict__ B,
              float* __restrict__ C, int M, int N, int K) {
    extern __shared__ float smbuf[];
    float* Asm = smbuf;
    float* Bsm = smbuf + NSTAGES * SA;

    const int tid  = threadIdx.x;
    const int wid  = tid >> 5;
    const int wm   = wid & 3;          // 4 warps along M
    const int wn   = wid >> 2;         // 2 warps along N
    const int mBase = blockIdx.y * BM;
    const int nBase = blockIdx.x * BN;

    // loaders: A = 128 rows x 4 float4-chunks; each thread does rows r and r+64
    const int a_row = tid >> 2;
    const int a_col = (tid & 3) << 2;
    // B = 16 rows x 32 float4-chunks; each thread does rows r and r+8
    const int b_row = tid >> 5;
    const int b_col = (tid & 31) << 2;

    const float* Ag0 = A + (size_t)(mBase + a_row) * K + a_col;
    const float* Ag1 = Ag0 + (size_t)64 * K;
    const float* Bg0 = B + (size_t)b_row * N + nBase + b_col;
    const float* Bg1 = Bg0 + (size_t)8 * N;

    float* sa0 = Asm + a_row * APITCH + a_col;
    float* sa1 = Asm + (a_row + 64) * APITCH + a_col;
    float* sb0 = Bsm + b_row * BPITCH + b_col;
    float* sb1 = Bsm + (b_row + 8) * BPITCH + b_col;

    const int KT = K / BK;

    // prefetch NSTAGES-1 stages
    for (int s = 0; s < NSTAGES - 1; s++) {
        int k0 = s * BK;
        __pipeline_memcpy_async(sa0 + s * SA, Ag0 + k0, 16);
        __pipeline_memcpy_async(sa1 + s * SA, Ag1 + k0, 16);
        __pipeline_memcpy_async(sb0 + s * SB, Bg0 + (size_t)k0 * N, 16);
        __pipeline_memcpy_async(sb1 + s * SB, Bg1 + (size_t)k0 * N, 16);
        __pipeline_commit();
    }

    wmma::fragment<wmma::accumulator, 16, 16, 8, float> acc[2][4];
    for (int i = 0; i < 2; i++)
        for (int j = 0; j < 4; j++)
            wmma::fill_fragment(acc[i][j], 0.0f);

    for (int kt = 0; kt < KT; kt++) {
        __pipeline_wait_prior(NSTAGES - 2);
        __syncthreads();
        const int st = kt & (NSTAGES - 1);
        const float* Ast = Asm + st * SA + (wm * 32) * APITCH;
        const float* Bst = Bsm + st * SB + wn * 64;

        for (int ks = 0; ks < BK / 8; ks++) {
            wmma::fragment<wmma::matrix_a, 16, 16, 8, wmma::precision::tf32, wmma::row_major> af[2];
            wmma::fragment<wmma::matrix_b, 16, 16, 8, wmma::precision::tf32, wmma::row_major> bf[4];
            wmma::load_matrix_sync(af[0], Ast + ks * 8, APITCH);
            wmma::load_matrix_sync(af[1], Ast + 16 * APITCH + ks * 8, APITCH);
            for (int nf = 0; nf < 4; nf++)
                wmma::load_matrix_sync(bf[nf], Bst + (ks * 8) * BPITCH + nf * 16, BPITCH);
            for (int mf = 0; mf < 2; mf++)
                for (int nf = 0; nf < 4; nf++)
                    wmma::mma_sync(acc[mf][nf], af[mf], bf[nf], acc[mf][nf]);
        }

        int ktn = kt + NSTAGES - 1;
        if (ktn < KT) {
            int s = ktn & (NSTAGES - 1);
            int k0 = ktn * BK;
            __pipeline_memcpy_async(sa0 + s * SA, Ag0 + k0, 16);
            __pipeline_memcpy_async(sa1 + s * SA, Ag1 + k0, 16);
            __pipeline_memcpy_async(sb0 + s * SB, Bg0 + (size_t)k0 * N, 16);
            __pipeline_memcpy_async(sb1 + s * SB, Bg1 + (size_t)k0 * N, 16);
        }
        __pipeline_commit();
    }

    // epilogue: direct fragment stores to C
    for (int mf = 0; mf < 2; mf++) {
        int r = mBase + wm * 32 + mf * 16;
        for (int nf = 0; nf < 4; nf++) {
            int cc = nBase + wn * 64 + nf * 16;
            wmma::store_matrix_sync(&C[(size_t)r * N + cc], acc[mf][nf], N, wmma::mem_row_major);
        }
    }
}

// ---------------- RGCN window aggregation (mean per relation) --------------
__global__ void rgcn_agg(const int* __restrict__ spk, const float* __restrict__ b_rgcn) {
    int i = blockIdx.x;
    int c = threadIdx.x;
    int p = i & (LL - 1);
    int dlo = (p < WIN) ? -p : -WIN;
    int dhi = ((LL - 1 - p) < WIN) ? (LL - 1 - p) : WIN;
    int si = spk[i];
    float s0 = 0.f, s1 = 0.f;
    int c0 = 0, c1 = 0;
    for (int d = dlo; d <= dhi; d++) {
        int j = i + d;
        int r = si & spk[j];
        float v = g_t_all[(size_t)j * 1024 + r * 256 + c];
        if (r) { s1 += v; c1++; } else { s0 += v; c0++; }
    }
    float h = g_t_all[(size_t)i * 1024 + 512 + c] + b_rgcn[c]
            + s0 / (float)(c0 > 0 ? c0 : 1)
            + s1 / (float)(c1 > 0 ? c1 : 1);
    g_hc[(size_t)i * 512 + 256 + c] = wmma::__float_to_tf32(h);  // feeds TF32 GEMM2
}

// ---------------- GraphConv neighbor add-aggregation -----------------------
__global__ void graph_sum() {
    int i = blockIdx.x;
    int c = threadIdx.x;
    int p = i & (LL - 1);
    int dlo = (p < WIN) ? -p : -WIN;
    int dhi = ((LL - 1 - p) < WIN) ? (LL - 1 - p) : WIN;
    float s = 0.f;
    for (int d = dlo; d <= dhi; d++)
        s += g_hc[(size_t)(i + d) * 512 + 256 + c];
    g_hc[(size_t)i * 512 + c] = wmma::__float_to_tf32(s);
}

// ---------------- classifier + cross-entropy loss --------------------------
__global__ void classify_loss(const float* __restrict__ b_rel,
                              const float* __restrict__ b_skip,
                              const float* __restrict__ W_cls,
                              const float* __restrict__ b_cls,
                              const int* __restrict__ labels,
                              float* __restrict__ out_logits) {
    int n = blockIdx.x * 8 + (threadIdx.x >> 5);
    int lane = threadIdx.x & 31;
    const float* zrow = g_z + (size_t)n * HH;
    const float* srow = g_t_all + (size_t)n * 1024 + 768;

    float acc[CC] = {0.f, 0.f, 0.f, 0.f, 0.f, 0.f, 0.f};
    for (int e = lane; e < HH; e += 32) {
        float pre = zrow[e] + srow[e] + b_rel[e] + b_skip[e];
#pragma unroll
        for (int cix = 0; cix < CC; cix++) acc[cix] = fmaf(pre, W_cls[e * CC + cix], acc[cix]);
    }
#pragma unroll
    for (int off = 16; off; off >>= 1)
#pragma unroll
        for (int cix = 0; cix < CC; cix++) acc[cix] += __shfl_xor_sync(0xffffffffu, acc[cix], off);
#pragma unroll
    for (int cix = 0; cix < CC; cix++) acc[cix] += b_cls[cix];

    if (out_logits != nullptr && lane < CC)
        out_logits[(size_t)n * CC + lane] = acc[lane];

    __shared__ float wloss[8];
    if (lane == 0) {
        float m = acc[0];
#pragma unroll
        for (int cix = 1; cix < CC; cix++) m = fmaxf(m, acc[cix]);
        float s = 0.f;
#pragma unroll
        for (int cix = 0; cix < CC; cix++) s += expf(acc[cix] - m);
        float lse = m + logf(s);
        wloss[threadIdx.x >> 5] = lse - acc[labels[n]];
    }
    __syncthreads();
    if (threadIdx.x == 0) {
        float t = 0.f;
#pragma unroll
        for (int w = 0; w < 8; w++) t += wloss[w];
        atomicAdd(&g_loss, t);
    }
}

__global__ void finalize_loss(float* __restrict__ dst) {
    *dst = g_loss * (1.0f / (float)NN);
}

// ---------------- host launcher --------------------------------------------
static float* sym_addr(const void* sym) {
    void* p = nullptr;
    cudaGetSymbolAddress(&p, sym);
    return (float*)p;
}

extern "C" void kernel_launch(void* const* d_in, const int* in_sizes, int n_in,
                              void* d_out, int out_size) {
    const float* input    = (const float*)d_in[0];
    const int*   speakers = (const int*)d_in[2];
    const int*   labels   = (const int*)d_in[3];
    const float* W_rgcn   = (const float*)d_in[6];
    const float* W_root   = (const float*)d_in[7];
    const float* b_rgcn   = (const float*)d_in[8];
    const float* W_rel    = (const float*)d_in[9];
    const float* b_rel    = (const float*)d_in[10];
    const float* W_grt    = (const float*)d_in[11];
    const float* W_skip   = (const float*)d_in[12];
    const float* b_skip   = (const float*)d_in[13];
    const float* W_cls    = (const float*)d_in[14];
    const float* b_cls    = (const float*)d_in[15];
    float* out = (float*)d_out;

    float* Ain   = sym_addr(g_Ain);
    float* t_all = sym_addr(g_t_all);
    float* hc    = sym_addr(g_hc);
    float* z     = sym_addr(g_z);
    float* Bcat1 = sym_addr(g_Bcat1);
    float* Bcat2 = sym_addr(g_Bcat2);

    cudaFuncSetAttribute(tf32gemm, cudaFuncAttributeMaxDynamicSharedMemorySize, SMEM_BYTES);

    // 1) weight concat (tf32-rounded) + loss zero
    prep_kernel<<<4096, 256>>>(W_rgcn, W_root, W_skip, W_rel, W_grt);

    // 1b) tf32-round the input matrix
    cvtA_kernel<<<2048, 256>>>((const float4*)input, (float4*)Ain);

    // 2) fused input GEMM (TF32 tensor): [32768,1024]@[1024,1024] -> [t0|t1|root|skip]
    tf32gemm<<<dim3(1024 / BN, NN / BM), 256, SMEM_BYTES>>>(Ain, Bcat1, t_all, NN, 1024, DIN);

    // 3) RGCN window mean-aggregation -> h
    rgcn_agg<<<NN, HH>>>(speakers, b_rgcn);

    // 4) GraphConv window add-aggregation -> neigh
    graph_sum<<<NN, HH>>>();

    // 5) [neigh|h] @ [W_rel;W_grt] (TF32 tensor): [32768,512]@[512,256]
    tf32gemm<<<dim3(256 / BN, NN / BM), 256, SMEM_BYTES>>>(hc, Bcat2, z, NN, 256, 512);

    // 6) classifier + loss
    float* logits = (out_size >= NN * CC) ? out : nullptr;
    classify_loss<<<NN / 8, 256>>>(b_rel, b_skip, W_cls, b_cls, labels, logits);

    // 7) loss scalar placement
    if (out_size == NN * CC + 1)       finalize_loss<<<1, 1>>>(out + (size_t)NN * CC);
    else if (out_size < NN * CC)       finalize_loss<<<1, 1>>>(out);
}

// round 9
// speedup vs baseline: 2.0011x; 1.1832x over previous
#include <cuda_runtime.h>
#include <cuda_bf16.h>
#include <cuda_pipeline.h>
#include <math.h>
#include <cstdint>

// Problem constants (fixed by the reference setup)
#define NB   128
#define LL   256
#define NN   (NB*LL)      // 32768 nodes
#define DIN  1024
#define HH   256
#define CC   7
#define WIN  4

// GEMM tiling
#define BM 128
#define BN 128
#define BK 16
#define APITCH 20         // floats per A smem row (pad 4 -> conflict-free LDSM)
#define BPITCH 136        // floats per B smem row (pad 8 -> conflict-free LDS)
#define NSTAGES 4
#define SA (BM*APITCH)    // 2560 floats per A stage
#define SB (BK*BPITCH)    // 2176 floats per B stage
#define SMEM_BYTES ((NSTAGES*(SA+SB))*4)   // 75776

// ---------------- scratch (device globals; no allocation allowed) ----------
__device__ __align__(256) float g_Ain[(size_t)NN * DIN];      // tf32-rounded input
__device__ __align__(256) float g_t_all[(size_t)NN * 1024];   // [t0|t1|root|skip]
__device__ __align__(256) float g_hc[(size_t)NN * 512];       // [neigh | h] tf32-rounded
__device__ __align__(256) float g_z[(size_t)NN * HH];
__device__ __align__(256) float g_Bcat1[1024 * 1024];         // [Wr0|Wr1|Wroot|Wskip] tf32
__device__ __align__(256) float g_Bcat2[512 * 256];           // [Wrel; Wgrt] tf32
__device__ float g_loss;

__device__ __forceinline__ float to_tf32(float x) {
    unsigned u;
    asm("cvt.rna.tf32.f32 %0, %1;" : "=r"(u) : "f"(x));
    return __uint_as_float(u);
}

// ---------------- PTX wrappers ---------------------------------------------
__device__ __forceinline__ void ldsm_x4(uint32_t& r0, uint32_t& r1, uint32_t& r2, uint32_t& r3,
                                        uint32_t addr) {
    asm volatile("ldmatrix.sync.aligned.m8n8.x4.shared.b16 {%0,%1,%2,%3}, [%4];"
                 : "=r"(r0), "=r"(r1), "=r"(r2), "=r"(r3)
                 : "r"(addr));
}
__device__ __forceinline__ void mma_tf32(float& c0, float& c1, float& c2, float& c3,
                                         uint32_t a0, uint32_t a1, uint32_t a2, uint32_t a3,
                                         uint32_t b0, uint32_t b1) {
    asm volatile("mma.sync.aligned.m16n8k8.row.col.f32.tf32.tf32.f32 "
                 "{%0,%1,%2,%3}, {%4,%5,%6,%7}, {%8,%9}, {%0,%1,%2,%3};"
                 : "+f"(c0), "+f"(c1), "+f"(c2), "+f"(c3)
                 : "r"(a0), "r"(a1), "r"(a2), "r"(a3), "r"(b0), "r"(b1));
}

// ---------------- prep: concatenated tf32 weights, zero loss ---------------
__global__ void prep_kernel(const float* __restrict__ Wrgcn,
                            const float* __restrict__ Wroot,
                            const float* __restrict__ Wskip,
                            const float* __restrict__ Wrel,
                            const float* __restrict__ Wgrt) {
    int idx = blockIdx.x * blockDim.x + threadIdx.x;
    if (idx == 0) g_loss = 0.0f;
    if (idx < 1024 * 1024) {
        int k = idx >> 10, col = idx & 1023;
        int g = col >> 8, c = col & 255;
        float v;
        if      (g == 0) v = Wrgcn[k * 256 + c];
        else if (g == 1) v = Wrgcn[262144 + k * 256 + c];
        else if (g == 2) v = Wroot[k * 256 + c];
        else             v = Wskip[k * 256 + c];
        g_Bcat1[idx] = to_tf32(v);
    }
    if (idx < 512 * 256) {
        int k = idx >> 8, c = idx & 255;
        g_Bcat2[idx] = to_tf32((k < 256) ? Wrel[k * 256 + c] : Wgrt[(k - 256) * 256 + c]);
    }
}

// ---------------- tf32-round the input matrix ------------------------------
__global__ void cvtA_kernel(const float4* __restrict__ in, float4* __restrict__ out) {
    int n4 = NN * DIN / 4;
    for (int i = blockIdx.x * blockDim.x + threadIdx.x; i < n4; i += gridDim.x * blockDim.x) {
        float4 v = in[i];
        v.x = to_tf32(v.x); v.y = to_tf32(v.y);
        v.z = to_tf32(v.z); v.w = to_tf32(v.w);
        out[i] = v;
    }
}

// ---------------- TF32 mma.sync GEMM, 128x128 tile, 4-stage cp.async -------
// blockIdx.x = N tile (fast-varying -> concurrent column tiles reuse A via L2)
// blockIdx.y = M tile
__global__ __launch_bounds__(256)
void tf32gemm(const float* __restrict__ A, const float* __restrict__ B,
              float* __restrict__ C, int M, int N, int K) {
    extern __shared__ float smbuf[];
    float* Asm = smbuf;
    float* Bsm = smbuf + NSTAGES * SA;

    const int tid  = threadIdx.x;
    const int lane = tid & 31, wid = tid >> 5;
    const int wm = wid >> 2, wn = wid & 3;       // 2 (m) x 4 (n) warps; warp tile 64x32
    const int mBase = blockIdx.y * BM;
    const int nBase = blockIdx.x * BN;

    const uint32_t sA_u = (uint32_t)__cvta_generic_to_shared(Asm);

    // loaders: A = 128 rows x 4 float4-chunks per row
    const int a_row = tid >> 2;
    const int a_col = (tid & 3) << 2;
    // B = 16 rows x 32 float4-chunks
    const int b_row = tid >> 5;
    const int b_col = (tid & 31) << 2;

    const float* Ag0 = A + (size_t)(mBase + a_row) * K + a_col;
    const float* Ag1 = Ag0 + (size_t)64 * K;
    const float* Bg0 = B + (size_t)b_row * N + nBase + b_col;
    const float* Bg1 = Bg0 + (size_t)8 * N;

    float* sa0 = Asm + a_row * APITCH + a_col;
    float* sa1 = Asm + (a_row + 64) * APITCH + a_col;
    float* sb0 = Bsm + b_row * BPITCH + b_col;
    float* sb1 = Bsm + (b_row + 8) * BPITCH + b_col;

    const int KT = K / BK;

    // prefetch NSTAGES-1 stages
    for (int s = 0; s < NSTAGES - 1; s++) {
        int k0 = s * BK;
        __pipeline_memcpy_async(sa0 + s * SA, Ag0 + k0, 16);
        __pipeline_memcpy_async(sa1 + s * SA, Ag1 + k0, 16);
        __pipeline_memcpy_async(sb0 + s * SB, Bg0 + (size_t)k0 * N, 16);
        __pipeline_memcpy_async(sb1 + s * SB, Bg1 + (size_t)k0 * N, 16);
        __pipeline_commit();
    }

    float acc[4][4][4];
#pragma unroll
    for (int i = 0; i < 4; i++)
#pragma unroll
        for (int j = 0; j < 4; j++)
#pragma unroll
            for (int k = 0; k < 4; k++) acc[i][j][k] = 0.0f;

    // ldmatrix lane->address mapping: 4 matrices = a0..a3 of m16n8k8 tf32
    const int lm_row = (lane & 7) + ((lane >> 3) & 1) * 8;
    const int lm_col = (lane >> 4) * 4;
    const uint32_t lmBase = sA_u + (uint32_t)((wm * 64 + lm_row) * APITCH + lm_col) * 4u;

    const int bl = lane & 3, bc = lane >> 2;

    for (int kt = 0; kt < KT; kt++) {
        __pipeline_wait_prior(NSTAGES - 2);
        __syncthreads();
        const int st = kt & (NSTAGES - 1);
        const float* Bst = Bsm + st * SB;
        const uint32_t aBase = lmBase + (uint32_t)(st * SA) * 4u;

#pragma unroll
        for (int ks = 0; ks < 2; ks++) {
            uint32_t afr[4][4];
#pragma unroll
            for (int mf = 0; mf < 4; mf++) {
                uint32_t ad = aBase + (uint32_t)(mf * 16 * APITCH + ks * 8) * 4u;
                ldsm_x4(afr[mf][0], afr[mf][1], afr[mf][2], afr[mf][3], ad);
            }
            uint32_t bfr[4][2];
            const float* Br0 = Bst + (ks * 8 + bl) * BPITCH + wn * 32 + bc;
            const float* Br1 = Br0 + 4 * BPITCH;
#pragma unroll
            for (int nf = 0; nf < 4; nf++) {
                bfr[nf][0] = __float_as_uint(Br0[nf * 8]);
                bfr[nf][1] = __float_as_uint(Br1[nf * 8]);
            }
#pragma unroll
            for (int mf = 0; mf < 4; mf++)
#pragma unroll
                for (int nf = 0; nf < 4; nf++)
                    mma_tf32(acc[mf][nf][0], acc[mf][nf][1], acc[mf][nf][2], acc[mf][nf][3],
                             afr[mf][0], afr[mf][1], afr[mf][2], afr[mf][3],
                             bfr[nf][0], bfr[nf][1]);
        }

        int ktn = kt + NSTAGES - 1;
        if (ktn < KT) {
            int s = ktn & (NSTAGES - 1);
            int k0 = ktn * BK;
            __pipeline_memcpy_async(sa0 + s * SA, Ag0 + k0, 16);
            __pipeline_memcpy_async(sa1 + s * SA, Ag1 + k0, 16);
            __pipeline_memcpy_async(sb0 + s * SB, Bg0 + (size_t)k0 * N, 16);
            __pipeline_memcpy_async(sb1 + s * SB, Bg1 + (size_t)k0 * N, 16);
        }
        __pipeline_commit();
    }

    // epilogue: c frag layout -> float2 stores
#pragma unroll
    for (int mf = 0; mf < 4; mf++) {
        int r = mBase + wm * 64 + mf * 16 + (lane >> 2);
#pragma unroll
        for (int nf = 0; nf < 4; nf++) {
            int cc = nBase + wn * 32 + nf * 8 + (lane & 3) * 2;
            *(float2*)&C[(size_t)r * N + cc]       = make_float2(acc[mf][nf][0], acc[mf][nf][1]);
            *(float2*)&C[(size_t)(r + 8) * N + cc] = make_float2(acc[mf][nf][2], acc[mf][nf][3]);
        }
    }
}

// ---------------- fused window aggregation (RGCN mean + GraphConv sum) -----
// block = (32-ch chunk, dialog); whole dialog's h kept in smem
__global__ void agg_fused(const int* __restrict__ spk, const float* __restrict__ b_rgcn) {
    __shared__ float hs[256][33];
    __shared__ int ss[256];
    const int dlg = blockIdx.y;
    const int tid = threadIdx.x;
    const int cl = tid & 31, n8 = tid >> 5;
    const int c = blockIdx.x * 32 + cl;

    ss[tid] = spk[dlg * 256 + tid];
    __syncthreads();

    const float bias = b_rgcn[c];
    const float* tb = g_t_all + (size_t)dlg * 256 * 1024;

    for (int ng = 0; ng < 32; ng++) {
        int n = n8 * 32 + ng;
        int dlo = (n < WIN) ? -n : -WIN;
        int dhi = ((255 - n) < WIN) ? (255 - n) : WIN;
        int si = ss[n];
        float s0 = 0.f, s1 = 0.f;
        int c0 = 0, c1 = 0;
        for (int d = dlo; d <= dhi; d++) {
            int j = n + d;
            int r = si & ss[j];
            float v = tb[(size_t)j * 1024 + r * 256 + c];
            if (r) { s1 += v; c1++; } else { s0 += v; c0++; }
        }
        float h = tb[(size_t)n * 1024 + 512 + c] + bias
                + s0 / (float)(c0 > 0 ? c0 : 1)
                + s1 / (float)(c1 > 0 ? c1 : 1);
        hs[n][cl] = h;
        g_hc[(size_t)(dlg * 256 + n) * 512 + 256 + c] = to_tf32(h);
    }
    __syncthreads();

    for (int ng = 0; ng < 32; ng++) {
        int n = n8 * 32 + ng;
        int dlo = (n < WIN) ? -n : -WIN;
        int dhi = ((255 - n) < WIN) ? (255 - n) : WIN;
        float s = 0.f;
        for (int d = dlo; d <= dhi; d++) s += hs[n + d][cl];
        g_hc[(size_t)(dlg * 256 + n) * 512 + c] = to_tf32(s);
    }
}

// ---------------- classifier + cross-entropy loss --------------------------
__global__ void classify_loss(const float* __restrict__ b_rel,
                              const float* __restrict__ b_skip,
                              const float* __restrict__ W_cls,
                              const float* __restrict__ b_cls,
                              const int* __restrict__ labels,
                              float* __restrict__ out_logits) {
    int n = blockIdx.x * 8 + (threadIdx.x >> 5);
    int lane = threadIdx.x & 31;
    const float* zrow = g_z + (size_t)n * HH;
    const float* srow = g_t_all + (size_t)n * 1024 + 768;

    float acc[CC] = {0.f, 0.f, 0.f, 0.f, 0.f, 0.f, 0.f};
    for (int e = lane; e < HH; e += 32) {
        float pre = zrow[e] + srow[e] + b_rel[e] + b_skip[e];
#pragma unroll
        for (int cix = 0; cix < CC; cix++) acc[cix] = fmaf(pre, W_cls[e * CC + cix], acc[cix]);
    }
#pragma unroll
    for (int off = 16; off; off >>= 1)
#pragma unroll
        for (int cix = 0; cix < CC; cix++) acc[cix] += __shfl_xor_sync(0xffffffffu, acc[cix], off);
#pragma unroll
    for (int cix = 0; cix < CC; cix++) acc[cix] += b_cls[cix];

    if (out_logits != nullptr && lane < CC)
        out_logits[(size_t)n * CC + lane] = acc[lane];

    __shared__ float wloss[8];
    if (lane == 0) {
        float m = acc[0];
#pragma unroll
        for (int cix = 1; cix < CC; cix++) m = fmaxf(m, acc[cix]);
        float s = 0.f;
#pragma unroll
        for (int cix = 0; cix < CC; cix++) s += expf(acc[cix] - m);
        float lse = m + logf(s);
        wloss[threadIdx.x >> 5] = lse - acc[labels[n]];
    }
    __syncthreads();
    if (threadIdx.x == 0) {
        float t = 0.f;
#pragma unroll
        for (int w = 0; w < 8; w++) t += wloss[w];
        atomicAdd(&g_loss, t);
    }
}

__global__ void finalize_loss(float* __restrict__ dst) {
    *dst = g_loss * (1.0f / (float)NN);
}

// ---------------- host launcher --------------------------------------------
template <typename T>
static T* sym_addr(const void* sym) {
    void* p = nullptr;
    cudaGetSymbolAddress(&p, sym);
    return (T*)p;
}

extern "C" void kernel_launch(void* const* d_in, const int* in_sizes, int n_in,
                              void* d_out, int out_size) {
    const float* input    = (const float*)d_in[0];
    const int*   speakers = (const int*)d_in[2];
    const int*   labels   = (const int*)d_in[3];
    const float* W_rgcn   = (const float*)d_in[6];
    const float* W_root   = (const float*)d_in[7];
    const float* b_rgcn   = (const float*)d_in[8];
    const float* W_rel    = (const float*)d_in[9];
    const float* b_rel    = (const float*)d_in[10];
    const float* W_grt    = (const float*)d_in[11];
    const float* W_skip   = (const float*)d_in[12];
    const float* b_skip   = (const float*)d_in[13];
    const float* W_cls    = (const float*)d_in[14];
    const float* b_cls    = (const float*)d_in[15];
    float* out = (float*)d_out;

    float* Ain   = sym_addr<float>(g_Ain);
    float* t_all = sym_addr<float>(g_t_all);
    float* hc    = sym_addr<float>(g_hc);
    float* z     = sym_addr<float>(g_z);
    float* Bcat1 = sym_addr<float>(g_Bcat1);
    float* Bcat2 = sym_addr<float>(g_Bcat2);

    cudaFuncSetAttribute(tf32gemm, cudaFuncAttributeMaxDynamicSharedMemorySize, SMEM_BYTES);

    // 1) weight concat (tf32-rounded) + loss zero
    prep_kernel<<<4096, 256>>>(W_rgcn, W_root, W_skip, W_rel, W_grt);

    // 2) tf32-round the input matrix
    cvtA_kernel<<<2048, 256>>>((const float4*)input, (float4*)Ain);

    // 3) fused input GEMM (TF32 mma.sync): [32768,1024]@[1024,1024]
    tf32gemm<<<dim3(1024 / BN, NN / BM), 256, SMEM_BYTES>>>(Ain, Bcat1, t_all, NN, 1024, DIN);

    // 4) fused RGCN mean + GraphConv sum -> hc [neigh|h]
    agg_fused<<<dim3(8, 128), 256>>>(speakers, b_rgcn);

    // 5) [neigh|h] @ [W_rel;W_grt]: [32768,512]@[512,256]
    tf32gemm<<<dim3(256 / BN, NN / BM), 256, SMEM_BYTES>>>(hc, Bcat2, z, NN, 256, 512);

    // 6) classifier + loss
    float* logits = (out_size >= NN * CC) ? out : nullptr;
    classify_loss<<<NN / 8, 256>>>(b_rel, b_skip, W_cls, b_cls, labels, logits);

    // 7) loss scalar placement
    if (out_size == NN * CC + 1)       finalize_loss<<<1, 1>>>(out + (size_t)NN * CC);
    else if (out_size < NN * CC)       finalize_loss<<<1, 1>>>(out);
}

// round 13
// speedup vs baseline: 3.3535x; 1.6759x over previous
#include <cuda_runtime.h>
#include <cuda_bf16.h>
#include <cuda_pipeline.h>
#include <math.h>
#include <cstdint>

// Problem constants (fixed by the reference setup)
#define NB   128
#define LL   256
#define NN   (NB*LL)      // 32768 nodes
#define DIN  1024
#define HH   256
#define CC   7
#define WIN  4

// GEMM tiling
#define BM 128
#define BN 128
#define BK 16
#define APITCH 20         // floats per A smem row (pad 4 -> conflict-free LDSM)
#define BPITCH 136        // floats per B smem row (pad 8 -> conflict-free LDS)
#define NSTAGES 4
#define SA (BM*APITCH)    // 2560 floats per A stage
#define SB (BK*BPITCH)    // 2176 floats per B stage
#define SMEM_BYTES ((NSTAGES*(SA+SB))*4)   // 75776 -> 2 CTAs/SM on 228KB

// ---------------- scratch (device globals; no allocation allowed) ----------
__device__ __align__(256) float g_Ain[(size_t)NN * DIN];      // tf32-rounded input
__device__ __align__(256) float g_t_all[(size_t)NN * 1024];   // [t0|t1|root|skip]
__device__ __align__(256) float g_hc[(size_t)NN * 512];       // [neigh | h] tf32-rounded
__device__ __align__(256) float g_z[(size_t)NN * HH];
__device__ __align__(256) float g_Bcat1[1024 * 1024];         // [Wr0|Wr1|Wroot|Wskip] tf32
__device__ __align__(256) float g_Bcat2[512 * 256];           // [Wrel; Wgrt] tf32
__device__ float g_loss;

__device__ __forceinline__ float to_tf32(float x) {
    unsigned u;
    asm("cvt.rna.tf32.f32 %0, %1;" : "=r"(u) : "f"(x));
    return __uint_as_float(u);
}

// ---------------- PTX wrappers ---------------------------------------------
__device__ __forceinline__ void ldsm_x4(uint32_t& r0, uint32_t& r1, uint32_t& r2, uint32_t& r3,
                                        uint32_t addr) {
    asm volatile("ldmatrix.sync.aligned.m8n8.x4.shared.b16 {%0,%1,%2,%3}, [%4];"
                 : "=r"(r0), "=r"(r1), "=r"(r2), "=r"(r3)
                 : "r"(addr));
}
__device__ __forceinline__ void mma_tf32(float& c0, float& c1, float& c2, float& c3,
                                         uint32_t a0, uint32_t a1, uint32_t a2, uint32_t a3,
                                         uint32_t b0, uint32_t b1) {
    asm volatile("mma.sync.aligned.m16n8k8.row.col.f32.tf32.tf32.f32 "
                 "{%0,%1,%2,%3}, {%4,%5,%6,%7}, {%8,%9}, {%0,%1,%2,%3};"
                 : "+f"(c0), "+f"(c1), "+f"(c2), "+f"(c3)
                 : "r"(a0), "r"(a1), "r"(a2), "r"(a3), "r"(b0), "r"(b1));
}

// ---------------- prep: concatenated tf32 weights, zero loss ---------------
__global__ void prep_kernel(const float* __restrict__ Wrgcn,
                            const float* __restrict__ Wroot,
                            const float* __restrict__ Wskip,
                            const float* __restrict__ Wrel,
                            const float* __restrict__ Wgrt) {
    int idx = blockIdx.x * blockDim.x + threadIdx.x;
    if (idx == 0) g_loss = 0.0f;
    if (idx < 1024 * 1024) {
        int k = idx >> 10, col = idx & 1023;
        int g = col >> 8, c = col & 255;
        float v;
        if      (g == 0) v = Wrgcn[k * 256 + c];
        else if (g == 1) v = Wrgcn[262144 + k * 256 + c];
        else if (g == 2) v = Wroot[k * 256 + c];
        else             v = Wskip[k * 256 + c];
        g_Bcat1[idx] = to_tf32(v);
    }
    if (idx < 512 * 256) {
        int k = idx >> 8, c = idx & 255;
        g_Bcat2[idx] = to_tf32((k < 256) ? Wrel[k * 256 + c] : Wgrt[(k - 256) * 256 + c]);
    }
}

// ---------------- tf32-round the input matrix ------------------------------
__global__ void cvtA_kernel(const float4* __restrict__ in, float4* __restrict__ out) {
    int n4 = NN * DIN / 4;
    for (int i = blockIdx.x * blockDim.x + threadIdx.x; i < n4; i += gridDim.x * blockDim.x) {
        float4 v = in[i];
        v.x = to_tf32(v.x); v.y = to_tf32(v.y);
        v.z = to_tf32(v.z); v.w = to_tf32(v.w);
        out[i] = v;
    }
}

// ---------------- TF32 mma.sync GEMM, 128x128 tile, 4-stage cp.async -------
// blockIdx.x = N tile (fast-varying -> concurrent column tiles reuse A via L2)
// blockIdx.y = M tile
__global__ __launch_bounds__(256, 2)
void tf32gemm(const float* __restrict__ A, const float* __restrict__ B,
              float* __restrict__ C, int M, int N, int K) {
    extern __shared__ float smbuf[];
    float* Asm = smbuf;
    float* Bsm = smbuf + NSTAGES * SA;

    const int tid  = threadIdx.x;
    const int lane = tid & 31, wid = tid >> 5;
    const int wm = wid >> 2, wn = wid & 3;       // 2 (m) x 4 (n) warps; warp tile 64x32
    const int mBase = blockIdx.y * BM;
    const int nBase = blockIdx.x * BN;

    const uint32_t sA_u = (uint32_t)__cvta_generic_to_shared(Asm);

    // loaders: A = 128 rows x 4 float4-chunks per row
    const int a_row = tid >> 2;
    const int a_col = (tid & 3) << 2;
    // B = 16 rows x 32 float4-chunks
    const int b_row = tid >> 5;
    const int b_col = (tid & 31) << 2;

    const float* Ag0 = A + (size_t)(mBase + a_row) * K + a_col;
    const float* Ag1 = Ag0 + (size_t)64 * K;
    const float* Bg0 = B + (size_t)b_row * N + nBase + b_col;
    const float* Bg1 = Bg0 + (size_t)8 * N;

    float* sa0 = Asm + a_row * APITCH + a_col;
    float* sa1 = Asm + (a_row + 64) * APITCH + a_col;
    float* sb0 = Bsm + b_row * BPITCH + b_col;
    float* sb1 = Bsm + (b_row + 8) * BPITCH + b_col;

    const int KT = K / BK;

    // prefetch NSTAGES-1 stages
    for (int s = 0; s < NSTAGES - 1; s++) {
        int k0 = s * BK;
        __pipeline_memcpy_async(sa0 + s * SA, Ag0 + k0, 16);
        __pipeline_memcpy_async(sa1 + s * SA, Ag1 + k0, 16);
        __pipeline_memcpy_async(sb0 + s * SB, Bg0 + (size_t)k0 * N, 16);
        __pipeline_memcpy_async(sb1 + s * SB, Bg1 + (size_t)k0 * N, 16);
        __pipeline_commit();
    }

    float acc[4][4][4];
#pragma unroll
    for (int i = 0; i < 4; i++)
#pragma unroll
        for (int j = 0; j < 4; j++)
#pragma unroll
            for (int k = 0; k < 4; k++) acc[i][j][k] = 0.0f;

    // ldmatrix lane->address mapping: 4 matrices = a0..a3 of m16n8k8 tf32
    const int lm_row = (lane & 7) + ((lane >> 3) & 1) * 8;
    const int lm_col = (lane >> 4) * 4;
    const uint32_t lmBase = sA_u + (uint32_t)((wm * 64 + lm_row) * APITCH + lm_col) * 4u;

    const int bl = lane & 3, bc = lane >> 2;

    for (int kt = 0; kt < KT; kt++) {
        __pipeline_wait_prior(NSTAGES - 2);
        __syncthreads();
        const int st = kt & (NSTAGES - 1);
        const float* Bst = Bsm + st * SB;
        const uint32_t aBase = lmBase + (uint32_t)(st * SA) * 4u;

#pragma unroll
        for (int ks = 0; ks < 2; ks++) {
            uint32_t afr[4][4];
#pragma unroll
            for (int mf = 0; mf < 4; mf++) {
                uint32_t ad = aBase + (uint32_t)(mf * 16 * APITCH + ks * 8) * 4u;
                ldsm_x4(afr[mf][0], afr[mf][1], afr[mf][2], afr[mf][3], ad);
            }
            uint32_t bfr[4][2];
            const float* Br0 = Bst + (ks * 8 + bl) * BPITCH + wn * 32 + bc;
            const float* Br1 = Br0 + 4 * BPITCH;
#pragma unroll
            for (int nf = 0; nf < 4; nf++) {
                bfr[nf][0] = __float_as_uint(Br0[nf * 8]);
                bfr[nf][1] = __float_as_uint(Br1[nf * 8]);
            }
#pragma unroll
            for (int mf = 0; mf < 4; mf++)
#pragma unroll
                for (int nf = 0; nf < 4; nf++)
                    mma_tf32(acc[mf][nf][0], acc[mf][nf][1], acc[mf][nf][2], acc[mf][nf][3],
                             afr[mf][0], afr[mf][1], afr[mf][2], afr[mf][3],
                             bfr[nf][0], bfr[nf][1]);
        }

        int ktn = kt + NSTAGES - 1;
        if (ktn < KT) {
            int s = ktn & (NSTAGES - 1);
            int k0 = ktn * BK;
            __pipeline_memcpy_async(sa0 + s * SA, Ag0 + k0, 16);
            __pipeline_memcpy_async(sa1 + s * SA, Ag1 + k0, 16);
            __pipeline_memcpy_async(sb0 + s * SB, Bg0 + (size_t)k0 * N, 16);
            __pipeline_memcpy_async(sb1 + s * SB, Bg1 + (size_t)k0 * N, 16);
        }
        __pipeline_commit();
    }

    // epilogue: c frag layout -> float2 stores
#pragma unroll
    for (int mf = 0; mf < 4; mf++) {
        int r = mBase + wm * 64 + mf * 16 + (lane >> 2);
#pragma unroll
        for (int nf = 0; nf < 4; nf++) {
            int cc = nBase + wn * 32 + nf * 8 + (lane & 3) * 2;
            *(float2*)&C[(size_t)r * N + cc]       = make_float2(acc[mf][nf][0], acc[mf][nf][1]);
            *(float2*)&C[(size_t)(r + 8) * N + cc] = make_float2(acc[mf][nf][2], acc[mf][nf][3]);
        }
    }
}

// ---------------- RGCN window aggregation (mean per relation) --------------
// one block per node, 256 threads = channels (measured 98us; latency-optimal)
__global__ void rgcn_agg(const int* __restrict__ spk, const float* __restrict__ b_rgcn) {
    int i = blockIdx.x;
    int c = threadIdx.x;
    int p = i & (LL - 1);
    int dlo = (p < WIN) ? -p : -WIN;
    int dhi = ((LL - 1 - p) < WIN) ? (LL - 1 - p) : WIN;
    int si = spk[i];
    float s0 = 0.f, s1 = 0.f;
    int c0 = 0, c1 = 0;
    for (int d = dlo; d <= dhi; d++) {
        int j = i + d;
        int r = si & spk[j];
        float v = g_t_all[(size_t)j * 1024 + r * 256 + c];
        if (r) { s1 += v; c1++; } else { s0 += v; c0++; }
    }
    float h = g_t_all[(size_t)i * 1024 + 512 + c] + b_rgcn[c]
            + s0 / (float)(c0 > 0 ? c0 : 1)
            + s1 / (float)(c1 > 0 ? c1 : 1);
    g_hc[(size_t)i * 512 + 256 + c] = to_tf32(h);   // feeds TF32 GEMM2
}

// ---------------- GraphConv neighbor add-aggregation -----------------------
__global__ void graph_sum() {
    int i = blockIdx.x;
    int c = threadIdx.x;
    int p = i & (LL - 1);
    int dlo = (p < WIN) ? -p : -WIN;
    int dhi = ((LL - 1 - p) < WIN) ? (LL - 1 - p) : WIN;
    float s = 0.f;
    for (int d = dlo; d <= dhi; d++)
        s += g_hc[(size_t)(i + d) * 512 + 256 + c];
    g_hc[(size_t)i * 512 + c] = to_tf32(s);
}

// ---------------- classifier + cross-entropy loss --------------------------
__global__ void classify_loss(const float* __restrict__ b_rel,
                              const float* __restrict__ b_skip,
                              const float* __restrict__ W_cls,
                              const float* __restrict__ b_cls,
                              const int* __restrict__ labels,
                              float* __restrict__ out_logits) {
    int n = blockIdx.x * 8 + (threadIdx.x >> 5);
    int lane = threadIdx.x & 31;
    const float* zrow = g_z + (size_t)n * HH;
    const float* srow = g_t_all + (size_t)n * 1024 + 768;

    float acc[CC] = {0.f, 0.f, 0.f, 0.f, 0.f, 0.f, 0.f};
    for (int e = lane; e < HH; e += 32) {
        float pre = zrow[e] + srow[e] + b_rel[e] + b_skip[e];
#pragma unroll
        for (int cix = 0; cix < CC; cix++) acc[cix] = fmaf(pre, W_cls[e * CC + cix], acc[cix]);
    }
#pragma unroll
    for (int off = 16; off; off >>= 1)
#pragma unroll
        for (int cix = 0; cix < CC; cix++) acc[cix] += __shfl_xor_sync(0xffffffffu, acc[cix], off);
#pragma unroll
    for (int cix = 0; cix < CC; cix++) acc[cix] += b_cls[cix];

    if (out_logits != nullptr && lane < CC)
        out_logits[(size_t)n * CC + lane] = acc[lane];

    __shared__ float wloss[8];
    if (lane == 0) {
        float m = acc[0];
#pragma unroll
        for (int cix = 1; cix < CC; cix++) m = fmaxf(m, acc[cix]);
        float s = 0.f;
#pragma unroll
        for (int cix = 0; cix < CC; cix++) s += expf(acc[cix] - m);
        float lse = m + logf(s);
        wloss[threadIdx.x >> 5] = lse - acc[labels[n]];
    }
    __syncthreads();
    if (threadIdx.x == 0) {
        float t = 0.f;
#pragma unroll
        for (int w = 0; w < 8; w++) t += wloss[w];
        atomicAdd(&g_loss, t);
    }
}

__global__ void finalize_loss(float* __restrict__ dst) {
    *dst = g_loss * (1.0f / (float)NN);
}

// ---------------- host launcher --------------------------------------------
template <typename T>
static T* sym_addr(const void* sym) {
    void* p = nullptr;
    cudaGetSymbolAddress(&p, sym);
    return (T*)p;
}

extern "C" void kernel_launch(void* const* d_in, const int* in_sizes, int n_in,
                              void* d_out, int out_size) {
    const float* input    = (const float*)d_in[0];
    const int*   speakers = (const int*)d_in[2];
    const int*   labels   = (const int*)d_in[3];
    const float* W_rgcn   = (const float*)d_in[6];
    const float* W_root   = (const float*)d_in[7];
    const float* b_rgcn   = (const float*)d_in[8];
    const float* W_rel    = (const float*)d_in[9];
    const float* b_rel    = (const float*)d_in[10];
    const float* W_grt    = (const float*)d_in[11];
    const float* W_skip   = (const float*)d_in[12];
    const float* b_skip   = (const float*)d_in[13];
    const float* W_cls    = (const float*)d_in[14];
    const float* b_cls    = (const float*)d_in[15];
    float* out = (float*)d_out;

    float* Ain   = sym_addr<float>(g_Ain);
    float* t_all = sym_addr<float>(g_t_all);
    float* hc    = sym_addr<float>(g_hc);
    float* z     = sym_addr<float>(g_z);
    float* Bcat1 = sym_addr<float>(g_Bcat1);
    float* Bcat2 = sym_addr<float>(g_Bcat2);

    cudaFuncSetAttribute(tf32gemm, cudaFuncAttributeMaxDynamicSharedMemorySize, SMEM_BYTES);

    // 1) weight concat (tf32-rounded) + loss zero
    prep_kernel<<<4096, 256>>>(W_rgcn, W_root, W_skip, W_rel, W_grt);

    // 2) tf32-round the input matrix
    cvtA_kernel<<<2048, 256>>>((const float4*)input, (float4*)Ain);

    // 3) fused input GEMM (TF32 mma.sync): [32768,1024]@[1024,1024]
    tf32gemm<<<dim3(1024 / BN, NN / BM), 256, SMEM_BYTES>>>(Ain, Bcat1, t_all, NN, 1024, DIN);

    // 4) RGCN window mean-aggregation -> h
    rgcn_agg<<<NN, HH>>>(speakers, b_rgcn);

    // 5) GraphConv window add-aggregation -> neigh
    graph_sum<<<NN, HH>>>();

    // 6) [neigh|h] @ [W_rel;W_grt]: [32768,512]@[512,256]
    tf32gemm<<<dim3(256 / BN, NN / BM), 256, SMEM_BYTES>>>(hc, Bcat2, z, NN, 256, 512);

    // 7) classifier + loss
    float* logits = (out_size >= NN * CC) ? out : nullptr;
    classify_loss<<<NN / 8, 256>>>(b_rel, b_skip, W_cls, b_cls, labels, logits);

    // 8) loss scalar placement
    if (out_size == NN * CC + 1)       finalize_loss<<<1, 1>>>(out + (size_t)NN * CC);
    else if (out_size < NN * CC)       finalize_loss<<<1, 1>>>(out);
}

// round 14
// speedup vs baseline: 3.5953x; 1.0721x over previous
#include <cuda_runtime.h>
#include <cuda_bf16.h>
#include <cuda_pipeline.h>
#include <math.h>
#include <cstdint>

// Problem constants (fixed by the reference setup)
#define NB   128
#define LL   256
#define NN   (NB*LL)      // 32768 nodes
#define DIN  1024
#define HH   256
#define CC   7
#define WIN  4

// GEMM tiling: BK=32, 3-stage ring -> half the syncs of BK=16/4-stage
#define BM 128
#define BN 128
#define BK 32
#define APITCH 36         // floats per A smem row (32 + 4 pad -> conflict-free LDSM)
#define BPITCH 136        // floats per B smem row (128 + 8 pad -> conflict-free LDS)
#define NSTAGES 3
#define SA (BM*APITCH)    // 4608 floats per A stage
#define SB (BK*BPITCH)    // 4352 floats per B stage
#define SMEM_BYTES ((NSTAGES*(SA+SB))*4)   // 107520 -> 2 CTAs/SM on 228KB

// ---------------- scratch (device globals; no allocation allowed) ----------
__device__ __align__(256) float g_Ain[(size_t)NN * DIN];      // tf32-rounded input
__device__ __align__(256) float g_t_all[(size_t)NN * 1024];   // [t0|t1|root|skip]
__device__ __align__(256) float g_hc[(size_t)NN * 512];       // [neigh | h] tf32-rounded
__device__ __align__(256) float g_z[(size_t)NN * HH];
__device__ __align__(256) float g_Bcat1[1024 * 1024];         // [Wr0|Wr1|Wroot|Wskip] tf32
__device__ __align__(256) float g_Bcat2[512 * 256];           // [Wrel; Wgrt] tf32
__device__ float g_loss;

__device__ __forceinline__ float to_tf32(float x) {
    unsigned u;
    asm("cvt.rna.tf32.f32 %0, %1;" : "=r"(u) : "f"(x));
    return __uint_as_float(u);
}

// ---------------- PTX wrappers ---------------------------------------------
__device__ __forceinline__ void ldsm_x4(uint32_t& r0, uint32_t& r1, uint32_t& r2, uint32_t& r3,
                                        uint32_t addr) {
    asm volatile("ldmatrix.sync.aligned.m8n8.x4.shared.b16 {%0,%1,%2,%3}, [%4];"
                 : "=r"(r0), "=r"(r1), "=r"(r2), "=r"(r3)
                 : "r"(addr));
}
__device__ __forceinline__ void mma_tf32(float& c0, float& c1, float& c2, float& c3,
                                         uint32_t a0, uint32_t a1, uint32_t a2, uint32_t a3,
                                         uint32_t b0, uint32_t b1) {
    asm volatile("mma.sync.aligned.m16n8k8.row.col.f32.tf32.tf32.f32 "
                 "{%0,%1,%2,%3}, {%4,%5,%6,%7}, {%8,%9}, {%0,%1,%2,%3};"
                 : "+f"(c0), "+f"(c1), "+f"(c2), "+f"(c3)
                 : "r"(a0), "r"(a1), "r"(a2), "r"(a3), "r"(b0), "r"(b1));
}

// ---------------- prep: concatenated tf32 weights, zero loss ---------------
__global__ void prep_kernel(const float* __restrict__ Wrgcn,
                            const float* __restrict__ Wroot,
                            const float* __restrict__ Wskip,
                            const float* __restrict__ Wrel,
                            const float* __restrict__ Wgrt) {
    int idx = blockIdx.x * blockDim.x + threadIdx.x;
    if (idx == 0) g_loss = 0.0f;
    if (idx < 1024 * 1024) {
        int k = idx >> 10, col = idx & 1023;
        int g = col >> 8, c = col & 255;
        float v;
        if      (g == 0) v = Wrgcn[k * 256 + c];
        else if (g == 1) v = Wrgcn[262144 + k * 256 + c];
        else if (g == 2) v = Wroot[k * 256 + c];
        else             v = Wskip[k * 256 + c];
        g_Bcat1[idx] = to_tf32(v);
    }
    if (idx < 512 * 256) {
        int k = idx >> 8, c = idx & 255;
        g_Bcat2[idx] = to_tf32((k < 256) ? Wrel[k * 256 + c] : Wgrt[(k - 256) * 256 + c]);
    }
}

// ---------------- tf32-round the input matrix ------------------------------
__global__ void cvtA_kernel(const float4* __restrict__ in, float4* __restrict__ out) {
    int n4 = NN * DIN / 4;
    for (int i = blockIdx.x * blockDim.x + threadIdx.x; i < n4; i += gridDim.x * blockDim.x) {
        float4 v = in[i];
        v.x = to_tf32(v.x); v.y = to_tf32(v.y);
        v.z = to_tf32(v.z); v.w = to_tf32(v.w);
        out[i] = v;
    }
}

// ---------------- TF32 mma.sync GEMM, 128x128 tile, BK=32, 3-stage ---------
// blockIdx.x = N tile (fast-varying -> concurrent column tiles reuse A via L2)
// blockIdx.y = M tile
__global__ __launch_bounds__(256, 2)
void tf32gemm(const float* __restrict__ A, const float* __restrict__ B,
              float* __restrict__ C, int M, int N, int K) {
    extern __shared__ float smbuf[];
    float* Asm = smbuf;
    float* Bsm = smbuf + NSTAGES * SA;

    const int tid  = threadIdx.x;
    const int lane = tid & 31, wid = tid >> 5;
    const int wm = wid >> 2, wn = wid & 3;       // 2 (m) x 4 (n) warps; warp tile 64x32
    const int mBase = blockIdx.y * BM;
    const int nBase = blockIdx.x * BN;

    const uint32_t sA_u = (uint32_t)__cvta_generic_to_shared(Asm);

    // loaders: A = 128 rows x 8 float4-chunks (1024 float4, 4 per thread)
    //          B = 32 rows x 32 float4-chunks (1024 float4, 4 per thread)
    const int KT = K / BK;

    float acc[4][4][4];
#pragma unroll
    for (int i = 0; i < 4; i++)
#pragma unroll
        for (int j = 0; j < 4; j++)
#pragma unroll
            for (int k = 0; k < 4; k++) acc[i][j][k] = 0.0f;

    // loader index precompute (4 chunks each for A and B)
    int arow[4], acol[4], brow[4], bcol[4];
#pragma unroll
    for (int i = 0; i < 4; i++) {
        int idx = tid + i * 256;
        arow[i] = idx >> 3;            // 0..127
        acol[i] = (idx & 7) << 2;      // 0..28
        brow[i] = idx >> 5;            // 0..31
        bcol[i] = (idx & 31) << 2;     // 0..124
    }

    // prefetch NSTAGES-1 stages
#pragma unroll
    for (int s = 0; s < NSTAGES - 1; s++) {
        int k0 = s * BK;
#pragma unroll
        for (int i = 0; i < 4; i++) {
            __pipeline_memcpy_async(Asm + s * SA + arow[i] * APITCH + acol[i],
                                    A + (size_t)(mBase + arow[i]) * K + k0 + acol[i], 16);
            __pipeline_memcpy_async(Bsm + s * SB + brow[i] * BPITCH + bcol[i],
                                    B + (size_t)(k0 + brow[i]) * N + nBase + bcol[i], 16);
        }
        __pipeline_commit();
    }

    // ldmatrix lane->address mapping: 4 matrices = a0..a3 of m16n8k8 tf32
    const int lm_row = (lane & 7) + ((lane >> 3) & 1) * 8;
    const int lm_col = (lane >> 4) * 4;
    const uint32_t lmBase = sA_u + (uint32_t)((wm * 64 + lm_row) * APITCH + lm_col) * 4u;

    const int bl = lane & 3, bc = lane >> 2;

    int st = 0;
    for (int kt = 0; kt < KT; kt++) {
        __pipeline_wait_prior(NSTAGES - 2);
        __syncthreads();
        const float* Bst = Bsm + st * SB;
        const uint32_t aBase = lmBase + (uint32_t)(st * SA) * 4u;

#pragma unroll
        for (int ks = 0; ks < 4; ks++) {
            uint32_t afr[4][4];
#pragma unroll
            for (int mf = 0; mf < 4; mf++) {
                uint32_t ad = aBase + (uint32_t)(mf * 16 * APITCH + ks * 8) * 4u;
                ldsm_x4(afr[mf][0], afr[mf][1], afr[mf][2], afr[mf][3], ad);
            }
            uint32_t bfr[4][2];
            const float* Br0 = Bst + (ks * 8 + bl) * BPITCH + wn * 32 + bc;
            const float* Br1 = Br0 + 4 * BPITCH;
#pragma unroll
            for (int nf = 0; nf < 4; nf++) {
                bfr[nf][0] = __float_as_uint(Br0[nf * 8]);
                bfr[nf][1] = __float_as_uint(Br1[nf * 8]);
            }
#pragma unroll
            for (int mf = 0; mf < 4; mf++)
#pragma unroll
                for (int nf = 0; nf < 4; nf++)
                    mma_tf32(acc[mf][nf][0], acc[mf][nf][1], acc[mf][nf][2], acc[mf][nf][3],
                             afr[mf][0], afr[mf][1], afr[mf][2], afr[mf][3],
                             bfr[nf][0], bfr[nf][1]);
        }

        int ktn = kt + NSTAGES - 1;
        if (ktn < KT) {
            int s = ktn % NSTAGES;
            int k0 = ktn * BK;
#pragma unroll
            for (int i = 0; i < 4; i++) {
                __pipeline_memcpy_async(Asm + s * SA + arow[i] * APITCH + acol[i],
                                        A + (size_t)(mBase + arow[i]) * K + k0 + acol[i], 16);
                __pipeline_memcpy_async(Bsm + s * SB + brow[i] * BPITCH + bcol[i],
                                        B + (size_t)(k0 + brow[i]) * N + nBase + bcol[i], 16);
            }
        }
        __pipeline_commit();

        st++; if (st == NSTAGES) st = 0;
    }

    // epilogue: c frag layout -> float2 stores
#pragma unroll
    for (int mf = 0; mf < 4; mf++) {
        int r = mBase + wm * 64 + mf * 16 + (lane >> 2);
#pragma unroll
        for (int nf = 0; nf < 4; nf++) {
            int cc = nBase + wn * 32 + nf * 8 + (lane & 3) * 2;
            *(float2*)&C[(size_t)r * N + cc]       = make_float2(acc[mf][nf][0], acc[mf][nf][1]);
            *(float2*)&C[(size_t)(r + 8) * N + cc] = make_float2(acc[mf][nf][2], acc[mf][nf][3]);
        }
    }
}

// ---------------- RGCN window aggregation (mean per relation) --------------
// one block per node, 128 threads, float2 per thread (halved instruction count)
__global__ void rgcn_agg(const int* __restrict__ spk, const float* __restrict__ b_rgcn) {
    int i = blockIdx.x;
    int c = threadIdx.x * 2;
    int p = i & (LL - 1);
    int dlo = (p < WIN) ? -p : -WIN;
    int dhi = ((LL - 1 - p) < WIN) ? (LL - 1 - p) : WIN;
    int si = spk[i];
    float s0x = 0.f, s0y = 0.f, s1x = 0.f, s1y = 0.f;
    int c0 = 0, c1 = 0;
    for (int d = dlo; d <= dhi; d++) {
        int j = i + d;
        int r = si & spk[j];
        float2 v = *(const float2*)&g_t_all[(size_t)j * 1024 + r * 256 + c];
        if (r) { s1x += v.x; s1y += v.y; c1++; } else { s0x += v.x; s0y += v.y; c0++; }
    }
    float inv0 = 1.0f / (float)(c0 > 0 ? c0 : 1);
    float inv1 = 1.0f / (float)(c1 > 0 ? c1 : 1);
    float2 root = *(const float2*)&g_t_all[(size_t)i * 1024 + 512 + c];
    float2 bb   = *(const float2*)&b_rgcn[c];
    float hx = root.x + bb.x + s0x * inv0 + s1x * inv1;
    float hy = root.y + bb.y + s0y * inv0 + s1y * inv1;
    *(float2*)&g_hc[(size_t)i * 512 + 256 + c] = make_float2(to_tf32(hx), to_tf32(hy));
}

// ---------------- GraphConv neighbor add-aggregation (float4) --------------
__global__ void graph_sum() {
    int i = blockIdx.x;
    int c = threadIdx.x * 4;
    int p = i & (LL - 1);
    int dlo = (p < WIN) ? -p : -WIN;
    int dhi = ((LL - 1 - p) < WIN) ? (LL - 1 - p) : WIN;
    float sx = 0.f, sy = 0.f, sz = 0.f, sw = 0.f;
    for (int d = dlo; d <= dhi; d++) {
        float4 v = *(const float4*)&g_hc[(size_t)(i + d) * 512 + 256 + c];
        sx += v.x; sy += v.y; sz += v.z; sw += v.w;
    }
    *(float4*)&g_hc[(size_t)i * 512 + c] =
        make_float4(to_tf32(sx), to_tf32(sy), to_tf32(sz), to_tf32(sw));
}

// ---------------- classifier + cross-entropy loss --------------------------
__global__ void classify_loss(const float* __restrict__ b_rel,
                              const float* __restrict__ b_skip,
                              const float* __restrict__ W_cls,
                              const float* __restrict__ b_cls,
                              const int* __restrict__ labels,
                              float* __restrict__ out_logits) {
    int n = blockIdx.x * 8 + (threadIdx.x >> 5);
    int lane = threadIdx.x & 31;
    const float* zrow = g_z + (size_t)n * HH;
    const float* srow = g_t_all + (size_t)n * 1024 + 768;

    float acc[CC] = {0.f, 0.f, 0.f, 0.f, 0.f, 0.f, 0.f};
    for (int e = lane; e < HH; e += 32) {
        float pre = zrow[e] + srow[e] + b_rel[e] + b_skip[e];
#pragma unroll
        for (int cix = 0; cix < CC; cix++) acc[cix] = fmaf(pre, W_cls[e * CC + cix], acc[cix]);
    }
#pragma unroll
    for (int off = 16; off; off >>= 1)
#pragma unroll
        for (int cix = 0; cix < CC; cix++) acc[cix] += __shfl_xor_sync(0xffffffffu, acc[cix], off);
#pragma unroll
    for (int cix = 0; cix < CC; cix++) acc[cix] += b_cls[cix];

    if (out_logits != nullptr && lane < CC)
        out_logits[(size_t)n * CC + lane] = acc[lane];

    __shared__ float wloss[8];
    if (lane == 0) {
        float m = acc[0];
#pragma unroll
        for (int cix = 1; cix < CC; cix++) m = fmaxf(m, acc[cix]);
        float s = 0.f;
#pragma unroll
        for (int cix = 0; cix < CC; cix++) s += expf(acc[cix] - m);
        float lse = m + logf(s);
        wloss[threadIdx.x >> 5] = lse - acc[labels[n]];
    }
    __syncthreads();
    if (threadIdx.x == 0) {
        float t = 0.f;
#pragma unroll
        for (int w = 0; w < 8; w++) t += wloss[w];
        atomicAdd(&g_loss, t);
    }
}

__global__ void finalize_loss(float* __restrict__ dst) {
    *dst = g_loss * (1.0f / (float)NN);
}

// ---------------- host launcher --------------------------------------------
template <typename T>
static T* sym_addr(const void* sym) {
    void* p = nullptr;
    cudaGetSymbolAddress(&p, sym);
    return (T*)p;
}

extern "C" void kernel_launch(void* const* d_in, const int* in_sizes, int n_in,
                              void* d_out, int out_size) {
    const float* input    = (const float*)d_in[0];
    const int*   speakers = (const int*)d_in[2];
    const int*   labels   = (const int*)d_in[3];
    const float* W_rgcn   = (const float*)d_in[6];
    const float* W_root   = (const float*)d_in[7];
    const float* b_rgcn   = (const float*)d_in[8];
    const float* W_rel    = (const float*)d_in[9];
    const float* b_rel    = (const float*)d_in[10];
    const float* W_grt    = (const float*)d_in[11];
    const float* W_skip   = (const float*)d_in[12];
    const float* b_skip   = (const float*)d_in[13];
    const float* W_cls    = (const float*)d_in[14];
    const float* b_cls    = (const float*)d_in[15];
    float* out = (float*)d_out;

    float* Ain   = sym_addr<float>(g_Ain);
    float* t_all = sym_addr<float>(g_t_all);
    float* hc    = sym_addr<float>(g_hc);
    float* z     = sym_addr<float>(g_z);
    float* Bcat1 = sym_addr<float>(g_Bcat1);
    float* Bcat2 = sym_addr<float>(g_Bcat2);

    cudaFuncSetAttribute(tf32gemm, cudaFuncAttributeMaxDynamicSharedMemorySize, SMEM_BYTES);

    // 1) weight concat (tf32-rounded) + loss zero
    prep_kernel<<<4096, 256>>>(W_rgcn, W_root, W_skip, W_rel, W_grt);

    // 2) tf32-round the input matrix
    cvtA_kernel<<<2048, 256>>>((const float4*)input, (float4*)Ain);

    // 3) fused input GEMM (TF32 mma.sync): [32768,1024]@[1024,1024]
    tf32gemm<<<dim3(1024 / BN, NN / BM), 256, SMEM_BYTES>>>(Ain, Bcat1, t_all, NN, 1024, DIN);

    // 4) RGCN window mean-aggregation -> h (float2 vectorized)
    rgcn_agg<<<NN, HH / 2>>>(speakers, b_rgcn);

    // 5) GraphConv window add-aggregation -> neigh (float4 vectorized)
    graph_sum<<<NN, HH / 4>>>();

    // 6) [neigh|h] @ [W_rel;W_grt]: [32768,512]@[512,256]
    tf32gemm<<<dim3(256 / BN, NN / BM), 256, SMEM_BYTES>>>(hc, Bcat2, z, NN, 256, 512);

    // 7) classifier + loss
    float* logits = (out_size >= NN * CC) ? out : nullptr;
    classify_loss<<<NN / 8, 256>>>(b_rel, b_skip, W_cls, b_cls, labels, logits);

    // 8) loss scalar placement
    if (out_size == NN * CC + 1)       finalize_loss<<<1, 1>>>(out + (size_t)NN * CC);
    else if (out_size < NN * CC)       finalize_loss<<<1, 1>>>(out);
}